// round 2
// baseline (speedup 1.0000x reference)
#include <cuda_runtime.h>
#include <cuda_bf16.h>

#define TPB 256
#define MAX_B 64
#define MAX_ATOMS 100000

// Padded position scratch: one float4 per atom per batch -> every gather is a
// single aligned 16B LDG.128 hitting exactly one 32B L2 sector.
__device__ float4 g_pos4[(size_t)MAX_B * MAX_ATOMS];

__global__ void zero_out_kernel(float* out, int n) {
    int i = blockIdx.x * blockDim.x + threadIdx.x;
    if (i < n) out[i] = 0.0f;
}

__global__ void transpose_kernel(const float* __restrict__ pos, int total) {
    int i = blockIdx.x * blockDim.x + threadIdx.x;
    if (i < total) {
        const float* p = pos + (size_t)i * 3;
        g_pos4[i] = make_float4(__ldg(p), __ldg(p + 1), __ldg(p + 2), 0.0f);
    }
}

__device__ __forceinline__ float3 load_pos(int base, int a) {
    float4 v = __ldg(&g_pos4[base + a]);
    return make_float3(v.x, v.y, v.z);
}

__device__ __forceinline__ float block_reduce(float v) {
    __shared__ float sh[TPB / 32];
    #pragma unroll
    for (int o = 16; o; o >>= 1) v += __shfl_down_sync(0xffffffffu, v, o);
    int w = threadIdx.x >> 5, l = threadIdx.x & 31;
    if (l == 0) sh[w] = v;
    __syncthreads();
    if (w == 0) {
        v = (l < TPB / 32) ? sh[l] : 0.0f;
        #pragma unroll
        for (int o = 16; o; o >>= 1) v += __shfl_down_sync(0xffffffffu, v, o);
    }
    return v;
}

__global__ void bond_kernel(const int* __restrict__ idcs,
                            const int* __restrict__ type,
                            const float* __restrict__ equ,
                            const float* __restrict__ kk,
                            int n, int n_atoms, float* __restrict__ out) {
    int i = blockIdx.x * blockDim.x + threadIdx.x;
    int b = blockIdx.y;
    int base = b * n_atoms;
    float e = 0.0f;
    if (i < n) {
        int a0 = __ldg(&idcs[2 * i]);
        int a1 = __ldg(&idcs[2 * i + 1]);
        float3 p0 = load_pos(base, a0);
        float3 p1 = load_pos(base, a1);
        float dx = p0.x - p1.x, dy = p0.y - p1.y, dz = p0.z - p1.z;
        float d = sqrtf(fmaf(dx, dx, fmaf(dy, dy, dz * dz)));
        int t = __ldg(&type[i]);
        float dd = d - __ldg(&equ[t]);
        e = __ldg(&kk[t]) * dd * dd;
    }
    float s = block_reduce(e);
    if (threadIdx.x == 0) atomicAdd(&out[b], s);
}

__global__ void angle_kernel(const int* __restrict__ idcs,
                             const int* __restrict__ type,
                             const float* __restrict__ equ,
                             const float* __restrict__ kk,
                             int n, int n_atoms, float* __restrict__ out) {
    int i = blockIdx.x * blockDim.x + threadIdx.x;
    int b = blockIdx.y;
    int base = b * n_atoms;
    float e = 0.0f;
    if (i < n) {
        int a0 = __ldg(&idcs[3 * i]);
        int a1 = __ldg(&idcs[3 * i + 1]);
        int a2 = __ldg(&idcs[3 * i + 2]);
        float3 p0 = load_pos(base, a0);
        float3 p1 = load_pos(base, a1);
        float3 p2 = load_pos(base, a2);
        float v1x = p0.x - p1.x, v1y = p0.y - p1.y, v1z = p0.z - p1.z;
        float v2x = p2.x - p1.x, v2y = p2.y - p1.y, v2z = p2.z - p1.z;
        float n1 = fmaf(v1x, v1x, fmaf(v1y, v1y, v1z * v1z));
        float n2 = fmaf(v2x, v2x, fmaf(v2y, v2y, v2z * v2z));
        float dot = fmaf(v1x, v2x, fmaf(v1y, v2y, v1z * v2z));
        float c = dot * rsqrtf(n1) * rsqrtf(n2);
        c = fminf(1.0f, fmaxf(-1.0f, c));
        float theta = acosf(c);
        int t = __ldg(&type[i]);
        float dd = theta - __ldg(&equ[t]);
        e = __ldg(&kk[t]) * dd * dd;
    }
    float s = block_reduce(e);
    if (threadIdx.x == 0) atomicAdd(&out[b], s);
}

__device__ __forceinline__ float dihedral(int base, int a0, int a1, int a2, int a3) {
    float3 p0 = load_pos(base, a0);
    float3 p1 = load_pos(base, a1);
    float3 p2 = load_pos(base, a2);
    float3 p3 = load_pos(base, a3);
    float b0x = p0.x - p1.x, b0y = p0.y - p1.y, b0z = p0.z - p1.z;
    float b1x = p2.x - p1.x, b1y = p2.y - p1.y, b1z = p2.z - p1.z;
    float b2x = p3.x - p2.x, b2y = p3.y - p2.y, b2z = p3.z - p2.z;
    float inv = rsqrtf(fmaf(b1x, b1x, fmaf(b1y, b1y, b1z * b1z)));
    b1x *= inv; b1y *= inv; b1z *= inv;
    float d0 = fmaf(b0x, b1x, fmaf(b0y, b1y, b0z * b1z));
    float d2 = fmaf(b2x, b1x, fmaf(b2y, b1y, b2z * b1z));
    float vx = b0x - d0 * b1x, vy = b0y - d0 * b1y, vz = b0z - d0 * b1z;
    float wx = b2x - d2 * b1x, wy = b2y - d2 * b1y, wz = b2z - d2 * b1z;
    float x = fmaf(vx, wx, fmaf(vy, wy, vz * wz));
    float cx = b1y * vz - b1z * vy;
    float cy = b1z * vx - b1x * vz;
    float cz = b1x * vy - b1y * vx;
    float y = fmaf(cx, wx, fmaf(cy, wy, cz * wz));
    return atan2f(y, x);
}

__global__ void improper_kernel(const int* __restrict__ idcs,
                                const int* __restrict__ type,
                                const float* __restrict__ equ,
                                const float* __restrict__ kk,
                                int n, int n_atoms, float* __restrict__ out) {
    int i = blockIdx.x * blockDim.x + threadIdx.x;
    int b = blockIdx.y;
    int base = b * n_atoms;
    float e = 0.0f;
    if (i < n) {
        int4 a = __ldg((const int4*)idcs + i);
        float phi = dihedral(base, a.x, a.y, a.z, a.w);
        int t = __ldg(&type[i]);
        float dd = phi - __ldg(&equ[t]);
        e = __ldg(&kk[t]) * dd * dd;
    }
    float s = block_reduce(e);
    if (threadIdx.x == 0) atomicAdd(&out[b], s);
}

__global__ void proper_kernel(const int* __restrict__ idcs,
                              const float* __restrict__ phase,
                              const float* __restrict__ cst,
                              const float* __restrict__ mul,
                              int n, int n_atoms, float* __restrict__ out) {
    int i = blockIdx.x * blockDim.x + threadIdx.x;
    int b = blockIdx.y;
    int base = b * n_atoms;
    float e = 0.0f;
    if (i < n) {
        int4 a = __ldg((const int4*)idcs + i);
        float phi = dihedral(base, a.x, a.y, a.z, a.w);
        float arg = fmaf(__ldg(&mul[i]), phi, -__ldg(&phase[i]));
        e = __ldg(&cst[i]) * (1.0f + cosf(arg));
    }
    float s = block_reduce(e);
    if (threadIdx.x == 0) atomicAdd(&out[b], s);
}

extern "C" void kernel_launch(void* const* d_in, const int* in_sizes, int n_in,
                              void* d_out, int out_size) {
    const float* pos            = (const float*)d_in[0];
    const int*   bond_idcs      = (const int*)d_in[1];
    const int*   bond_type      = (const int*)d_in[2];
    const float* equ_bond       = (const float*)d_in[3];
    const float* k_bond         = (const float*)d_in[4];
    const int*   angle_idcs     = (const int*)d_in[5];
    const int*   angle_type     = (const int*)d_in[6];
    const float* equ_angle      = (const float*)d_in[7];
    const float* k_angle        = (const float*)d_in[8];
    const int*   improper_idcs  = (const int*)d_in[9];
    const int*   improper_type  = (const int*)d_in[10];
    const float* equ_improper   = (const float*)d_in[11];
    const float* k_improper     = (const float*)d_in[12];
    const int*   proper_idcs    = (const int*)d_in[13];
    const float* proper_phase   = (const float*)d_in[14];
    const float* proper_const   = (const float*)d_in[15];
    const float* proper_mul     = (const float*)d_in[16];
    float* out = (float*)d_out;

    int B       = out_size;                 // 64
    int n_bond  = in_sizes[2];
    int n_angle = in_sizes[6];
    int n_improper = in_sizes[10];
    int n_proper   = in_sizes[14];
    int n_atoms = in_sizes[0] / (3 * B);

    zero_out_kernel<<<1, 64>>>(out, B);

    int total = B * n_atoms;
    transpose_kernel<<<(total + TPB - 1) / TPB, TPB>>>(pos, total);

    dim3 gb((n_bond + TPB - 1) / TPB, B);
    bond_kernel<<<gb, TPB>>>(bond_idcs, bond_type, equ_bond, k_bond,
                             n_bond, n_atoms, out);

    dim3 ga((n_angle + TPB - 1) / TPB, B);
    angle_kernel<<<ga, TPB>>>(angle_idcs, angle_type, equ_angle, k_angle,
                              n_angle, n_atoms, out);

    dim3 gi((n_improper + TPB - 1) / TPB, B);
    improper_kernel<<<gi, TPB>>>(improper_idcs, improper_type, equ_improper,
                                 k_improper, n_improper, n_atoms, out);

    dim3 gp((n_proper + TPB - 1) / TPB, B);
    proper_kernel<<<gp, TPB>>>(proper_idcs, proper_phase, proper_const,
                               proper_mul, n_proper, n_atoms, out);
}

// round 4
// speedup vs baseline: 3.4533x; 3.4533x over previous
#include <cuda_runtime.h>
#include <cuda_bf16.h>

#define TPB 256
#define MAX_ATOMS 100000
#define NB 64
#define NB2 32   // float2 pairs per atom
#define NWARP (TPB / 32)

// Batch-fastest position planes: x[atom][64] etc., stored as float2 pairs.
// Lane l of a warp covers batches 2l and 2l+1 -> every load is coalesced 256B.
__device__ float2 g_xp[(size_t)MAX_ATOMS * NB2];
__device__ float2 g_yp[(size_t)MAX_ATOMS * NB2];
__device__ float2 g_zp[(size_t)MAX_ATOMS * NB2];

__global__ void zero_out_kernel(float* out, int n) {
    int i = blockIdx.x * blockDim.x + threadIdx.x;
    if (i < n) out[i] = 0.0f;
}

// pos[b][atom][3] -> planes [atom][b]; writes fully coalesced (b fastest).
__global__ void transpose_kernel(const float* __restrict__ pos, int n_atoms, int total) {
    int tid = blockIdx.x * blockDim.x + threadIdx.x;
    if (tid < total) {
        int b = tid & 63;
        int atom = tid >> 6;
        const float* p = pos + ((size_t)b * n_atoms + atom) * 3;
        float x = __ldg(p), y = __ldg(p + 1), z = __ldg(p + 2);
        ((float*)g_xp)[atom * NB + b] = x;
        ((float*)g_yp)[atom * NB + b] = y;
        ((float*)g_zp)[atom * NB + b] = z;
    }
}

// ---- float2 elementwise helpers ----
__device__ __forceinline__ float2 f2sub(float2 a, float2 b) { return make_float2(a.x - b.x, a.y - b.y); }
__device__ __forceinline__ float2 f2mul(float2 a, float2 b) { return make_float2(a.x * b.x, a.y * b.y); }
__device__ __forceinline__ float2 f2fma(float2 a, float2 b, float2 c) {
    return make_float2(fmaf(a.x, b.x, c.x), fmaf(a.y, b.y, c.y));
}
__device__ __forceinline__ float2 f2nfma(float2 a, float2 b, float2 c) { // c - a*b
    return make_float2(fmaf(-a.x, b.x, c.x), fmaf(-a.y, b.y, c.y));
}
__device__ __forceinline__ float2 f2rsqrt(float2 a) { return make_float2(rsqrtf(a.x), rsqrtf(a.y)); }

__device__ __forceinline__ void load_atom(int a, int lane, float2& x, float2& y, float2& z) {
    int off = a * NB2 + lane;
    x = __ldg(&g_xp[off]);
    y = __ldg(&g_yp[off]);
    z = __ldg(&g_zp[off]);
}

__device__ __forceinline__ float2 f2dot3(float2 ax, float2 ay, float2 az,
                                         float2 bx, float2 by, float2 bz) {
    return f2fma(ax, bx, f2fma(ay, by, f2mul(az, bz)));
}

// dihedral for a batch-pair; returns phi for both batches
__device__ __forceinline__ float2 dihedral2(int a0, int a1, int a2, int a3, int lane) {
    float2 x0, y0, z0, x1, y1, z1, x2, y2, z2, x3, y3, z3;
    load_atom(a0, lane, x0, y0, z0);
    load_atom(a1, lane, x1, y1, z1);
    load_atom(a2, lane, x2, y2, z2);
    load_atom(a3, lane, x3, y3, z3);
    float2 b0x = f2sub(x0, x1), b0y = f2sub(y0, y1), b0z = f2sub(z0, z1);
    float2 b1x = f2sub(x2, x1), b1y = f2sub(y2, y1), b1z = f2sub(z2, z1);
    float2 b2x = f2sub(x3, x2), b2y = f2sub(y3, y2), b2z = f2sub(z3, z2);
    float2 inv = f2rsqrt(f2dot3(b1x, b1y, b1z, b1x, b1y, b1z));
    b1x = f2mul(b1x, inv); b1y = f2mul(b1y, inv); b1z = f2mul(b1z, inv);
    float2 d0 = f2dot3(b0x, b0y, b0z, b1x, b1y, b1z);
    float2 d2 = f2dot3(b2x, b2y, b2z, b1x, b1y, b1z);
    float2 vx = f2nfma(d0, b1x, b0x), vy = f2nfma(d0, b1y, b0y), vz = f2nfma(d0, b1z, b0z);
    float2 wx = f2nfma(d2, b1x, b2x), wy = f2nfma(d2, b1y, b2y), wz = f2nfma(d2, b1z, b2z);
    float2 x = f2dot3(vx, vy, vz, wx, wy, wz);
    float2 cx = f2sub(f2mul(b1y, vz), f2mul(b1z, vy));
    float2 cy = f2sub(f2mul(b1z, vx), f2mul(b1x, vz));
    float2 cz = f2sub(f2mul(b1x, vy), f2mul(b1y, vx));
    float2 y = f2dot3(cx, cy, cz, wx, wy, wz);
    return make_float2(atan2f(y.x, x.x), atan2f(y.y, x.y));
}

// One fused kernel; blockIdx.y selects the term category. Each warp evaluates
// one term for all 64 batches (lane l -> batches 2l, 2l+1) with a grid-stride
// loop over terms.
__global__ void energy_kernel(
    const int* __restrict__ bond_idcs, const int* __restrict__ bond_type,
    const float* __restrict__ equ_bond, const float* __restrict__ k_bond, int n_bond,
    const int* __restrict__ angle_idcs, const int* __restrict__ angle_type,
    const float* __restrict__ equ_angle, const float* __restrict__ k_angle, int n_angle,
    const int* __restrict__ improper_idcs, const int* __restrict__ improper_type,
    const float* __restrict__ equ_improper, const float* __restrict__ k_improper, int n_improper,
    const int* __restrict__ proper_idcs, const float* __restrict__ proper_phase,
    const float* __restrict__ proper_const, const float* __restrict__ proper_mul, int n_proper,
    float* __restrict__ out)
{
    int lane = threadIdx.x & 31;
    int warp = threadIdx.x >> 5;
    int warp_g = blockIdx.x * NWARP + warp;
    int nwarps = gridDim.x * NWARP;
    float2 e = make_float2(0.0f, 0.0f);

    if (blockIdx.y == 0) {          // bonds
        for (int t = warp_g; t < n_bond; t += nwarps) {
            int a0 = __ldg(&bond_idcs[2 * t]);
            int a1 = __ldg(&bond_idcs[2 * t + 1]);
            int ty = __ldg(&bond_type[t]);
            float eq = __ldg(&equ_bond[ty]);
            float kb = __ldg(&k_bond[ty]);
            float2 x0, y0, z0, x1, y1, z1;
            load_atom(a0, lane, x0, y0, z0);
            load_atom(a1, lane, x1, y1, z1);
            float2 dx = f2sub(x0, x1), dy = f2sub(y0, y1), dz = f2sub(z0, z1);
            float2 r2 = f2dot3(dx, dy, dz, dx, dy, dz);
            float ddx = sqrtf(r2.x) - eq;
            float ddy = sqrtf(r2.y) - eq;
            e.x = fmaf(kb * ddx, ddx, e.x);
            e.y = fmaf(kb * ddy, ddy, e.y);
        }
    } else if (blockIdx.y == 1) {   // angles
        for (int t = warp_g; t < n_angle; t += nwarps) {
            int a0 = __ldg(&angle_idcs[3 * t]);
            int a1 = __ldg(&angle_idcs[3 * t + 1]);
            int a2 = __ldg(&angle_idcs[3 * t + 2]);
            int ty = __ldg(&angle_type[t]);
            float eq = __ldg(&equ_angle[ty]);
            float ka = __ldg(&k_angle[ty]);
            float2 x0, y0, z0, x1, y1, z1, x2, y2, z2;
            load_atom(a0, lane, x0, y0, z0);
            load_atom(a1, lane, x1, y1, z1);
            load_atom(a2, lane, x2, y2, z2);
            float2 v1x = f2sub(x0, x1), v1y = f2sub(y0, y1), v1z = f2sub(z0, z1);
            float2 v2x = f2sub(x2, x1), v2y = f2sub(y2, y1), v2z = f2sub(z2, z1);
            float2 n1 = f2dot3(v1x, v1y, v1z, v1x, v1y, v1z);
            float2 n2 = f2dot3(v2x, v2y, v2z, v2x, v2y, v2z);
            float2 dt = f2dot3(v1x, v1y, v1z, v2x, v2y, v2z);
            float2 c = f2mul(f2mul(dt, f2rsqrt(n1)), f2rsqrt(n2));
            float cx = fminf(1.0f, fmaxf(-1.0f, c.x));
            float cy = fminf(1.0f, fmaxf(-1.0f, c.y));
            float ddx = acosf(cx) - eq;
            float ddy = acosf(cy) - eq;
            e.x = fmaf(ka * ddx, ddx, e.x);
            e.y = fmaf(ka * ddy, ddy, e.y);
        }
    } else if (blockIdx.y == 2) {   // impropers
        for (int t = warp_g; t < n_improper; t += nwarps) {
            int4 a = __ldg((const int4*)improper_idcs + t);
            int ty = __ldg(&improper_type[t]);
            float eq = __ldg(&equ_improper[ty]);
            float ki = __ldg(&k_improper[ty]);
            float2 phi = dihedral2(a.x, a.y, a.z, a.w, lane);
            float ddx = phi.x - eq;
            float ddy = phi.y - eq;
            e.x = fmaf(ki * ddx, ddx, e.x);
            e.y = fmaf(ki * ddy, ddy, e.y);
        }
    } else {                        // propers
        for (int t = warp_g; t < n_proper; t += nwarps) {
            int4 a = __ldg((const int4*)proper_idcs + t);
            float ph = __ldg(&proper_phase[t]);
            float cst = __ldg(&proper_const[t]);
            float ml = __ldg(&proper_mul[t]);
            float2 phi = dihedral2(a.x, a.y, a.z, a.w, lane);
            e.x += cst * (1.0f + cosf(fmaf(ml, phi.x, -ph)));
            e.y += cst * (1.0f + cosf(fmaf(ml, phi.y, -ph)));
        }
    }

    // Per-warp private slots, then fold: no shared-atomic serialization.
    __shared__ float sh[NWARP][NB];
    sh[warp][2 * lane]     = e.x;
    sh[warp][2 * lane + 1] = e.y;
    __syncthreads();
    if (threadIdx.x < NB) {
        float s = 0.0f;
        #pragma unroll
        for (int w = 0; w < NWARP; w++) s += sh[w][threadIdx.x];
        atomicAdd(&out[threadIdx.x], s);
    }
}

extern "C" void kernel_launch(void* const* d_in, const int* in_sizes, int n_in,
                              void* d_out, int out_size) {
    const float* pos            = (const float*)d_in[0];
    const int*   bond_idcs      = (const int*)d_in[1];
    const int*   bond_type      = (const int*)d_in[2];
    const float* equ_bond       = (const float*)d_in[3];
    const float* k_bond         = (const float*)d_in[4];
    const int*   angle_idcs     = (const int*)d_in[5];
    const int*   angle_type     = (const int*)d_in[6];
    const float* equ_angle      = (const float*)d_in[7];
    const float* k_angle        = (const float*)d_in[8];
    const int*   improper_idcs  = (const int*)d_in[9];
    const int*   improper_type  = (const int*)d_in[10];
    const float* equ_improper   = (const float*)d_in[11];
    const float* k_improper     = (const float*)d_in[12];
    const int*   proper_idcs    = (const int*)d_in[13];
    const float* proper_phase   = (const float*)d_in[14];
    const float* proper_const   = (const float*)d_in[15];
    const float* proper_mul     = (const float*)d_in[16];
    float* out = (float*)d_out;

    int B          = out_size;              // 64
    int n_bond     = in_sizes[2];
    int n_angle    = in_sizes[6];
    int n_improper = in_sizes[10];
    int n_proper   = in_sizes[14];
    int n_atoms    = in_sizes[0] / (3 * B);

    zero_out_kernel<<<1, 64>>>(out, B);

    int total = B * n_atoms;
    transpose_kernel<<<(total + TPB - 1) / TPB, TPB>>>(pos, n_atoms, total);

    dim3 grid(296, 4);
    energy_kernel<<<grid, TPB>>>(
        bond_idcs, bond_type, equ_bond, k_bond, n_bond,
        angle_idcs, angle_type, equ_angle, k_angle, n_angle,
        improper_idcs, improper_type, equ_improper, k_improper, n_improper,
        proper_idcs, proper_phase, proper_const, proper_mul, n_proper,
        out);
}

// round 5
// speedup vs baseline: 4.0830x; 1.1824x over previous
#include <cuda_runtime.h>
#include <cuda_bf16.h>

#define TPB 256
#define MAX_ATOMS 100000
#define NB 64
#define NB2 32   // float2 pairs per atom
#define NWARP (TPB / 32)
#define TR_ATOMS 32

// Batch-fastest position planes: x[atom][64] etc., stored as float2 pairs.
// Lane l of a warp covers batches 2l and 2l+1 -> every load is coalesced 256B.
__device__ float2 g_xp[(size_t)MAX_ATOMS * NB2];
__device__ float2 g_yp[(size_t)MAX_ATOMS * NB2];
__device__ float2 g_zp[(size_t)MAX_ATOMS * NB2];

// Tiled transpose: pos[b][atom][3] -> planes [atom][b].
// Per block: 32 atoms x 64 batches. Both gmem sides fully coalesced;
// smem tile padded (97) for conflict-free transposed reads.
// Also zeroes the output vector (block 0) so no separate zero kernel.
__global__ void transpose_kernel(const float* __restrict__ pos, int n_atoms,
                                 float* __restrict__ out) {
    __shared__ float tile[NB][TR_ATOMS * 3 + 1];   // [64][97]
    int tid = threadIdx.x;
    int atom_base = blockIdx.x * TR_ATOMS;

    if (blockIdx.x == 0 && tid < NB) out[tid] = 0.0f;

    int lim3 = n_atoms * 3;
    // read: for each batch b, 96 contiguous floats (32 atoms x 3 comps)
    #pragma unroll
    for (int idx = tid; idx < NB * TR_ATOMS * 3; idx += TPB) {
        int b = idx / (TR_ATOMS * 3);
        int r = idx - b * (TR_ATOMS * 3);
        int g = atom_base * 3 + r;
        if (g < lim3)
            tile[b][r] = __ldg(&pos[(size_t)b * lim3 + g]);
    }
    __syncthreads();
    // write: comp-major, b fastest -> coalesced 256B runs per (comp, atom)
    #pragma unroll
    for (int idx = tid; idx < 3 * TR_ATOMS * NB; idx += TPB) {
        int comp = idx >> 11;            // / 2048
        int rem  = idx & 2047;
        int atom = rem >> 6;             // / 64
        int b    = rem & 63;
        int ga = atom_base + atom;
        if (ga < n_atoms) {
            float v = tile[b][atom * 3 + comp];
            float* plane = (comp == 0) ? (float*)g_xp : (comp == 1) ? (float*)g_yp : (float*)g_zp;
            plane[(size_t)ga * NB + b] = v;
        }
    }
}

// ---- float2 elementwise helpers ----
__device__ __forceinline__ float2 f2sub(float2 a, float2 b) { return make_float2(a.x - b.x, a.y - b.y); }
__device__ __forceinline__ float2 f2mul(float2 a, float2 b) { return make_float2(a.x * b.x, a.y * b.y); }
__device__ __forceinline__ float2 f2fma(float2 a, float2 b, float2 c) {
    return make_float2(fmaf(a.x, b.x, c.x), fmaf(a.y, b.y, c.y));
}
__device__ __forceinline__ float2 f2nfma(float2 a, float2 b, float2 c) { // c - a*b
    return make_float2(fmaf(-a.x, b.x, c.x), fmaf(-a.y, b.y, c.y));
}
__device__ __forceinline__ float2 f2rsqrt(float2 a) { return make_float2(rsqrtf(a.x), rsqrtf(a.y)); }

__device__ __forceinline__ void load_atom(int a, int lane, float2& x, float2& y, float2& z) {
    int off = a * NB2 + lane;
    x = __ldg(&g_xp[off]);
    y = __ldg(&g_yp[off]);
    z = __ldg(&g_zp[off]);
}

__device__ __forceinline__ float2 f2dot3(float2 ax, float2 ay, float2 az,
                                         float2 bx, float2 by, float2 bz) {
    return f2fma(ax, bx, f2fma(ay, by, f2mul(az, bz)));
}

// dihedral for a batch-pair; returns phi for both batches
__device__ __forceinline__ float2 dihedral2(int a0, int a1, int a2, int a3, int lane) {
    float2 x0, y0, z0, x1, y1, z1, x2, y2, z2, x3, y3, z3;
    load_atom(a0, lane, x0, y0, z0);
    load_atom(a1, lane, x1, y1, z1);
    load_atom(a2, lane, x2, y2, z2);
    load_atom(a3, lane, x3, y3, z3);
    float2 b0x = f2sub(x0, x1), b0y = f2sub(y0, y1), b0z = f2sub(z0, z1);
    float2 b1x = f2sub(x2, x1), b1y = f2sub(y2, y1), b1z = f2sub(z2, z1);
    float2 b2x = f2sub(x3, x2), b2y = f2sub(y3, y2), b2z = f2sub(z3, z2);
    float2 inv = f2rsqrt(f2dot3(b1x, b1y, b1z, b1x, b1y, b1z));
    b1x = f2mul(b1x, inv); b1y = f2mul(b1y, inv); b1z = f2mul(b1z, inv);
    float2 d0 = f2dot3(b0x, b0y, b0z, b1x, b1y, b1z);
    float2 d2 = f2dot3(b2x, b2y, b2z, b1x, b1y, b1z);
    float2 vx = f2nfma(d0, b1x, b0x), vy = f2nfma(d0, b1y, b0y), vz = f2nfma(d0, b1z, b0z);
    float2 wx = f2nfma(d2, b1x, b2x), wy = f2nfma(d2, b1y, b2y), wz = f2nfma(d2, b1z, b2z);
    float2 x = f2dot3(vx, vy, vz, wx, wy, wz);
    float2 cx = f2sub(f2mul(b1y, vz), f2mul(b1z, vy));
    float2 cy = f2sub(f2mul(b1z, vx), f2mul(b1x, vz));
    float2 cz = f2sub(f2mul(b1x, vy), f2mul(b1y, vx));
    float2 y = f2dot3(cx, cy, cz, wx, wy, wz);
    return make_float2(atan2f(y.x, x.x), atan2f(y.y, x.y));
}

// One fused kernel, 1D grid partitioned by work-proportional category ranges.
// Each warp evaluates one term for all 64 batches (lane l -> batches 2l, 2l+1).
__global__ void energy_kernel(
    const int* __restrict__ bond_idcs, const int* __restrict__ bond_type,
    const float* __restrict__ equ_bond, const float* __restrict__ k_bond, int n_bond,
    const int* __restrict__ angle_idcs, const int* __restrict__ angle_type,
    const float* __restrict__ equ_angle, const float* __restrict__ k_angle, int n_angle,
    const int* __restrict__ improper_idcs, const int* __restrict__ improper_type,
    const float* __restrict__ equ_improper, const float* __restrict__ k_improper, int n_improper,
    const int* __restrict__ proper_idcs, const float* __restrict__ proper_phase,
    const float* __restrict__ proper_const, const float* __restrict__ proper_mul, int n_proper,
    int gb, int ga, int gi,      // cumulative block-range boundaries (bond, +angle, +improper)
    float* __restrict__ out)
{
    int lane = threadIdx.x & 31;
    int warp = threadIdx.x >> 5;

    int cat, bstart, bcount;
    int bx = blockIdx.x;
    if (bx < gb)      { cat = 0; bstart = 0;  bcount = gb; }
    else if (bx < ga) { cat = 1; bstart = gb; bcount = ga - gb; }
    else if (bx < gi) { cat = 2; bstart = ga; bcount = gi - ga; }
    else              { cat = 3; bstart = gi; bcount = gridDim.x - gi; }

    int warp_g = (bx - bstart) * NWARP + warp;
    int nwarps = bcount * NWARP;
    float2 e = make_float2(0.0f, 0.0f);

    if (cat == 0) {                 // bonds
        for (int t = warp_g; t < n_bond; t += nwarps) {
            int a0 = __ldg(&bond_idcs[2 * t]);
            int a1 = __ldg(&bond_idcs[2 * t + 1]);
            int ty = __ldg(&bond_type[t]);
            float eq = __ldg(&equ_bond[ty]);
            float kb = __ldg(&k_bond[ty]);
            float2 x0, y0, z0, x1, y1, z1;
            load_atom(a0, lane, x0, y0, z0);
            load_atom(a1, lane, x1, y1, z1);
            float2 dx = f2sub(x0, x1), dy = f2sub(y0, y1), dz = f2sub(z0, z1);
            float2 r2 = f2dot3(dx, dy, dz, dx, dy, dz);
            float ddx = sqrtf(r2.x) - eq;
            float ddy = sqrtf(r2.y) - eq;
            e.x = fmaf(kb * ddx, ddx, e.x);
            e.y = fmaf(kb * ddy, ddy, e.y);
        }
    } else if (cat == 1) {          // angles
        for (int t = warp_g; t < n_angle; t += nwarps) {
            int a0 = __ldg(&angle_idcs[3 * t]);
            int a1 = __ldg(&angle_idcs[3 * t + 1]);
            int a2 = __ldg(&angle_idcs[3 * t + 2]);
            int ty = __ldg(&angle_type[t]);
            float eq = __ldg(&equ_angle[ty]);
            float ka = __ldg(&k_angle[ty]);
            float2 x0, y0, z0, x1, y1, z1, x2, y2, z2;
            load_atom(a0, lane, x0, y0, z0);
            load_atom(a1, lane, x1, y1, z1);
            load_atom(a2, lane, x2, y2, z2);
            float2 v1x = f2sub(x0, x1), v1y = f2sub(y0, y1), v1z = f2sub(z0, z1);
            float2 v2x = f2sub(x2, x1), v2y = f2sub(y2, y1), v2z = f2sub(z2, z1);
            float2 n1 = f2dot3(v1x, v1y, v1z, v1x, v1y, v1z);
            float2 n2 = f2dot3(v2x, v2y, v2z, v2x, v2y, v2z);
            float2 dt = f2dot3(v1x, v1y, v1z, v2x, v2y, v2z);
            float2 c = f2mul(f2mul(dt, f2rsqrt(n1)), f2rsqrt(n2));
            float cx = fminf(1.0f, fmaxf(-1.0f, c.x));
            float cy = fminf(1.0f, fmaxf(-1.0f, c.y));
            float ddx = acosf(cx) - eq;
            float ddy = acosf(cy) - eq;
            e.x = fmaf(ka * ddx, ddx, e.x);
            e.y = fmaf(ka * ddy, ddy, e.y);
        }
    } else if (cat == 2) {          // impropers
        for (int t = warp_g; t < n_improper; t += nwarps) {
            int4 a = __ldg((const int4*)improper_idcs + t);
            int ty = __ldg(&improper_type[t]);
            float eq = __ldg(&equ_improper[ty]);
            float ki = __ldg(&k_improper[ty]);
            float2 phi = dihedral2(a.x, a.y, a.z, a.w, lane);
            float ddx = phi.x - eq;
            float ddy = phi.y - eq;
            e.x = fmaf(ki * ddx, ddx, e.x);
            e.y = fmaf(ki * ddy, ddy, e.y);
        }
    } else {                        // propers
        for (int t = warp_g; t < n_proper; t += nwarps) {
            int4 a = __ldg((const int4*)proper_idcs + t);
            float ph = __ldg(&proper_phase[t]);
            float cst = __ldg(&proper_const[t]);
            float ml = __ldg(&proper_mul[t]);
            float2 phi = dihedral2(a.x, a.y, a.z, a.w, lane);
            e.x += cst * (1.0f + cosf(fmaf(ml, phi.x, -ph)));
            e.y += cst * (1.0f + cosf(fmaf(ml, phi.y, -ph)));
        }
    }

    // Per-warp private slots, then fold: no shared-atomic serialization.
    __shared__ float sh[NWARP][NB];
    sh[warp][2 * lane]     = e.x;
    sh[warp][2 * lane + 1] = e.y;
    __syncthreads();
    if (threadIdx.x < NB) {
        float s = 0.0f;
        #pragma unroll
        for (int w = 0; w < NWARP; w++) s += sh[w][threadIdx.x];
        atomicAdd(&out[threadIdx.x], s);
    }
}

extern "C" void kernel_launch(void* const* d_in, const int* in_sizes, int n_in,
                              void* d_out, int out_size) {
    const float* pos            = (const float*)d_in[0];
    const int*   bond_idcs      = (const int*)d_in[1];
    const int*   bond_type      = (const int*)d_in[2];
    const float* equ_bond       = (const float*)d_in[3];
    const float* k_bond         = (const float*)d_in[4];
    const int*   angle_idcs     = (const int*)d_in[5];
    const int*   angle_type     = (const int*)d_in[6];
    const float* equ_angle      = (const float*)d_in[7];
    const float* k_angle        = (const float*)d_in[8];
    const int*   improper_idcs  = (const int*)d_in[9];
    const int*   improper_type  = (const int*)d_in[10];
    const float* equ_improper   = (const float*)d_in[11];
    const float* k_improper     = (const float*)d_in[12];
    const int*   proper_idcs    = (const int*)d_in[13];
    const float* proper_phase   = (const float*)d_in[14];
    const float* proper_const   = (const float*)d_in[15];
    const float* proper_mul     = (const float*)d_in[16];
    float* out = (float*)d_out;

    int B          = out_size;              // 64
    int n_bond     = in_sizes[2];
    int n_angle    = in_sizes[6];
    int n_improper = in_sizes[10];
    int n_proper   = in_sizes[14];
    int n_atoms    = in_sizes[0] / (3 * B);

    int tr_blocks = (n_atoms + TR_ATOMS - 1) / TR_ATOMS;
    transpose_kernel<<<tr_blocks, TPB>>>(pos, n_atoms, out);

    // Work-proportional block partition over 1184 blocks (8 per SM on 148 SMs).
    // Weights = atom-loads: bond 2*n_bond, angle 3*n_angle, improper 4*n_improper,
    // proper 4*n_proper.
    long long wb = 2LL * n_bond, wa = 3LL * n_angle, wi = 4LL * n_improper, wp = 4LL * n_proper;
    long long wt = wb + wa + wi + wp;
    int total_blocks = 1184;
    int gb = (int)(total_blocks * wb / wt); if (gb < 1) gb = 1;
    int ga_ = (int)(total_blocks * wa / wt); if (ga_ < 1) ga_ = 1;
    int gi_ = (int)(total_blocks * wi / wt); if (gi_ < 1) gi_ = 1;
    int ga = gb + ga_;
    int gi = ga + gi_;
    if (gi >= total_blocks) { gi = total_blocks - 1; }  // ensure proper gets >=1

    energy_kernel<<<total_blocks, TPB>>>(
        bond_idcs, bond_type, equ_bond, k_bond, n_bond,
        angle_idcs, angle_type, equ_angle, k_angle, n_angle,
        improper_idcs, improper_type, equ_improper, k_improper, n_improper,
        proper_idcs, proper_phase, proper_const, proper_mul, n_proper,
        gb, ga, gi, out);
}